// round 12
// baseline (speedup 1.0000x reference)
#include <cuda_runtime.h>
#include <cuda_bf16.h>
#include <cstdint>
#include <math.h>

#define S_TOK 32768
#define CDIM 256
#define NEXP 16
#define HID 1024
#define CAP 4096
#define NPIX (8*256*64*64)

// ---------------- scratch (device globals; no allocs allowed) ----------------
__device__ float g_t[S_TOK * CDIM];           // tokens [S,256]
__device__ float g_buf[NEXP * CAP * CDIM];    // dispatched expert input
__device__ float g_h[NEXP * CAP * HID];       // hidden
__device__ float g_eo[NEXP * CAP * CDIM];     // expert output
__device__ float g_y0[S_TOK * CDIM];          // channel MoE combined
__device__ float g_y1[S_TOK * CDIM];          // spatial MoE combined
__device__ int   g_idx1[S_TOK], g_idx2[S_TOK];
__device__ float g_gate1[S_TOK], g_gate2[S_TOK];
__device__ unsigned char g_keep2a[S_TOK];
__device__ float g_c1[S_TOK], g_c2[S_TOK];
__device__ int   g_d1[S_TOK], g_d2[S_TOK];
__device__ float g_probsum[NEXP];
__device__ int   g_tot1[NEXP];
__device__ int   g_cnt[NEXP];
__device__ float g_a0[S_TOK];
__device__ float g_loss[2];

// ---------------- token build: t[s,c] = x[b,c,h,w] + audio[b,c] -------------
__global__ void build_t_kernel(const float* __restrict__ x,
                               const float* __restrict__ audio) {
    __shared__ float sm[32][33];
    int b = blockIdx.x, c0 = blockIdx.y * 32, hw0 = blockIdx.z * 32;
    int tx = threadIdx.x, ty = threadIdx.y;
    sm[ty][tx] = x[((size_t)(b * CDIM + c0 + ty)) * 4096 + hw0 + tx];
    __syncthreads();
    int c = c0 + tx;
    g_t[((size_t)(b * 4096 + hw0 + ty)) * CDIM + c] = __fadd_rn(sm[tx][ty], audio[b * CDIM + c]);
}

__global__ void zero16_kernel() {
    if (threadIdx.x < NEXP) g_probsum[threadIdx.x] = 0.f;
}

// ---------------- routing ----------------------------------------------------
// logits: cublas gemv/skinny-GEMM realization — 32 lane-partials, each a
// serial FMA over stride-32 elements (lane j: c = j, j+32, ..., j+224),
// combined by a shfl_down-order binary tree (offsets 16,8,4,2,1).
// softmax: expf numerators (monotone => ordering fixed by logits), fp32
// serial sum + divide. decisions: exact first-max-wins argmax (post-division
// ties -> lower index, matching jnp.argmax), masked 2nd argmax, > 0.2f.
__global__ void route_kernel(const float* __restrict__ wg) {
    __shared__ float wgs[NEXP][CDIM + 1];  // [e][c], padded: conflict-free
    __shared__ float ts[16][CDIM];         // 16 tokens per block
    __shared__ float lg[16][NEXP];
    __shared__ float pr[16][NEXP];
    int tid = threadIdx.x;                 // 256
    int e = tid & 15, tok = tid >> 4;
    for (int i = tid; i < CDIM * NEXP; i += 256) wgs[i & 15][i >> 4] = wg[i];  // wg[c*16+e]
    int s0 = blockIdx.x * 16;
    for (int i = tid; i < 16 * CDIM; i += 256)
        ts[i >> 8][i & 255] = g_t[(size_t)(s0 + (i >> 8)) * CDIM + (i & 255)];
    __syncthreads();

    // 32 strided lane-partials (serial FMA each), then shfl_down tree order
    float part[32];
#pragma unroll
    for (int j = 0; j < 32; j++) {
        float a = 0.f;
#pragma unroll
        for (int i = 0; i < 8; i++) {
            int c = j + 32 * i;
            a = __fmaf_rn(ts[tok][c], wgs[e][c], a);
        }
        part[j] = a;
    }
#pragma unroll
    for (int off = 16; off > 0; off >>= 1)
#pragma unroll
        for (int j = 0; j < 16; j++)
            if (j < off) part[j] = __fadd_rn(part[j], part[j + off]);
    lg[tok][e] = part[0];
    __syncthreads();

    if (e == 0) {
        float l[NEXP];
        float m = -INFINITY;
        for (int j = 0; j < NEXP; j++) { l[j] = lg[tok][j]; m = fmaxf(m, l[j]); }
        float ex[NEXP];
        float sum = 0.f;
        for (int j = 0; j < NEXP; j++) {
            ex[j] = expf(__fsub_rn(l[j], m));
            sum = __fadd_rn(sum, ex[j]);
        }
        float p[NEXP];
        int i1 = 0; float b1 = -1.f;
        for (int j = 0; j < NEXP; j++) {
            p[j] = __fdiv_rn(ex[j], sum);
            pr[tok][j] = p[j];
            if (p[j] > b1) { b1 = p[j]; i1 = j; }   // first max wins (ties -> lowest idx)
        }
        int i2 = -1; float b2 = -2.f;
        for (int j = 0; j < NEXP; j++) {
            if (j == i1) continue;
            if (p[j] > b2) { b2 = p[j]; i2 = j; }
        }
        int s = s0 + tok;
        g_idx1[s] = i1; g_idx2[s] = i2;
        g_gate1[s] = p[i1]; g_gate2[s] = p[i2];
        g_keep2a[s] = (p[i2] > 0.2f) ? 1 : 0;
    }
    __syncthreads();
    if (tok == 0) {
        float a = 0.f;
        for (int j = 0; j < 16; j++) a += pr[j][e];
        atomicAdd(&g_probsum[e], a);
    }
}

// ---------------- ordered per-expert positions (single-block scan) ----------
__global__ void scan_kernel() {
    __shared__ unsigned short c1s[512 * NEXP];  // 16KB
    __shared__ unsigned short c2s[512 * NEXP];  // 16KB
    __shared__ int tot1s[NEXP], tot2s[NEXP];
    int t = threadIdx.x;  // 512
    for (int e = 0; e < NEXP; e++) { c1s[t * NEXP + e] = 0; c2s[t * NEXP + e] = 0; }
    __syncthreads();
    int s0 = t * 64;
    for (int i = 0; i < 64; i++) {
        int s = s0 + i;
        c1s[t * NEXP + g_idx1[s]]++;
        if (g_keep2a[s]) c2s[t * NEXP + g_idx2[s]]++;
    }
    __syncthreads();
    int w = t >> 5, lane = t & 31;
    {
        unsigned carry1 = 0, carry2 = 0;
        for (int chunk = 0; chunk < 16; chunk++) {
            int idx = (chunk * 32 + lane) * NEXP + w;
            unsigned v1 = c1s[idx], v2 = c2s[idx];
            unsigned s1 = v1, s2 = v2;
            for (int o = 1; o < 32; o <<= 1) {
                unsigned n1 = __shfl_up_sync(0xffffffffu, s1, o);
                unsigned n2 = __shfl_up_sync(0xffffffffu, s2, o);
                if (lane >= o) { s1 += n1; s2 += n2; }
            }
            c1s[idx] = (unsigned short)(s1 - v1 + carry1);
            c2s[idx] = (unsigned short)(s2 - v2 + carry2);
            carry1 += __shfl_sync(0xffffffffu, s1, 31);
            carry2 += __shfl_sync(0xffffffffu, s2, 31);
        }
        if (lane == 31) { tot1s[w] = (int)carry1; tot2s[w] = (int)carry2; }
    }
    __syncthreads();
    for (int i = 0; i < 64; i++) {
        int s = s0 + i;
        int e1 = g_idx1[s];
        int pos1 = (int)(c1s[t * NEXP + e1]++);
        int e2 = g_idx2[s];
        int k2a = (int)g_keep2a[s];
        int pos2 = 0;
        if (k2a) pos2 = (int)(c2s[t * NEXP + e2]++) + tot1s[e2];
        int keep1 = (pos1 < CAP);
        int keep2 = k2a && (pos2 < CAP);
        float gate1 = g_gate1[s], gate2 = g_gate2[s];
        float denom = __fadd_rn(__fadd_rn(gate1, __fmul_rn(gate2, (float)k2a)), 1e-9f);
        g_c1[s] = keep1 ? __fdiv_rn(gate1, denom) : 0.f;
        g_c2[s] = keep2 ? __fdiv_rn(gate2, denom) : 0.f;
        g_d1[s] = keep1 ? (e1 * CAP + pos1) : -1;
        g_d2[s] = keep2 ? (e2 * CAP + pos2) : -1;
    }
    if (t < NEXP) {
        g_tot1[t] = tot1s[t];
        int used = tot1s[t] + tot2s[t];
        g_cnt[t] = used > CAP ? CAP : used;
    }
}

__global__ void loss_partial_kernel(int m) {
    if (threadIdx.x == 0) {
        float l = 0.f;
        for (int e = 0; e < NEXP; e++)
            l += ((float)g_tot1[e] / (float)S_TOK) * (g_probsum[e] / (float)S_TOK);
        g_loss[m] = l * (float)NEXP * 0.01f;
    }
}

// ---------------- dispatch: scatter token rows into expert buffers ----------
__global__ void scatter_kernel() {
    int gw = (blockIdx.x * blockDim.x + threadIdx.x) >> 5;
    int lane = threadIdx.x & 31;
    if (gw >= S_TOK) return;
    int s = gw;
    const float4* trow = (const float4*)(g_t + (size_t)s * CDIM);
    float4 v0 = trow[lane], v1 = trow[lane + 32];
    int d1 = g_d1[s], d2 = g_d2[s];
    if (d1 >= 0) {
        float4* o = (float4*)(g_buf + (size_t)d1 * CDIM);
        o[lane] = v0; o[lane + 32] = v1;
    }
    if (d2 >= 0) {
        float4* o = (float4*)(g_buf + (size_t)d2 * CDIM);
        o[lane] = v0; o[lane + 32] = v1;
    }
}

// ---------------- tiled SGEMM: 128x128 tile, 8x8 per thread (fp32) ----------
template<int KDIM, int NDIM, bool PHASE1>
__global__ void __launch_bounds__(256)
gemm_kernel(const float* __restrict__ Bw, const float* __restrict__ bias) {
    const int e = blockIdx.z;
    if ((int)(blockIdx.y * 128) >= g_cnt[e]) return;   // skip empty row tiles
    const float* A = (PHASE1 ? g_buf : g_h) + (size_t)e * CAP * KDIM + (size_t)blockIdx.y * 128 * KDIM;
    const float* B = Bw + (size_t)e * KDIM * NDIM + blockIdx.x * 128;
    float* Cp = (PHASE1 ? g_h : g_eo) + (size_t)e * CAP * NDIM
              + (size_t)blockIdx.y * 128 * NDIM + blockIdx.x * 128;
    __shared__ float As[16][132];
    __shared__ float Bs[16][128];
    int tid = threadIdx.x;
    int ty = tid >> 4, tx = tid & 15;
    int ar = tid >> 2, ak = (tid & 3) * 4;
    int br = tid >> 5, bc = (tid & 31) * 4;
    float acc[8][8];
#pragma unroll
    for (int i = 0; i < 8; i++)
#pragma unroll
        for (int j = 0; j < 8; j++) acc[i][j] = 0.f;

    for (int k0 = 0; k0 < KDIM; k0 += 16) {
        float4 a0 = *(const float4*)(A + (size_t)ar * KDIM + k0 + ak);
        float4 a1 = *(const float4*)(A + (size_t)(ar + 64) * KDIM + k0 + ak);
        As[ak + 0][ar] = a0.x; As[ak + 1][ar] = a0.y; As[ak + 2][ar] = a0.z; As[ak + 3][ar] = a0.w;
        As[ak + 0][ar + 64] = a1.x; As[ak + 1][ar + 64] = a1.y; As[ak + 2][ar + 64] = a1.z; As[ak + 3][ar + 64] = a1.w;
        *(float4*)(&Bs[br][bc])     = *(const float4*)(B + (size_t)(k0 + br) * NDIM + bc);
        *(float4*)(&Bs[br + 8][bc]) = *(const float4*)(B + (size_t)(k0 + br + 8) * NDIM + bc);
        __syncthreads();
#pragma unroll
        for (int kk = 0; kk < 16; kk++) {
            float a[8], b[8];
#pragma unroll
            for (int i = 0; i < 8; i++) a[i] = As[kk][ty * 8 + i];
#pragma unroll
            for (int j = 0; j < 8; j++) b[j] = Bs[kk][tx * 8 + j];
#pragma unroll
            for (int i = 0; i < 8; i++)
#pragma unroll
                for (int j = 0; j < 8; j++) acc[i][j] += a[i] * b[j];
        }
        __syncthreads();
    }
    const float* bv = bias + e * NDIM + blockIdx.x * 128;
#pragma unroll
    for (int i = 0; i < 8; i++) {
        int row = ty * 8 + i;
        float* orow = Cp + (size_t)row * NDIM;
#pragma unroll
        for (int j = 0; j < 8; j += 4) {
            float4 v;
            v.x = acc[i][j + 0] + bv[tx * 8 + j + 0];
            v.y = acc[i][j + 1] + bv[tx * 8 + j + 1];
            v.z = acc[i][j + 2] + bv[tx * 8 + j + 2];
            v.w = acc[i][j + 3] + bv[tx * 8 + j + 3];
            if (PHASE1) {
                v.x = v.x > 0.f ? v.x : 0.01f * v.x;
                v.y = v.y > 0.f ? v.y : 0.01f * v.y;
                v.z = v.z > 0.f ? v.z : 0.01f * v.z;
                v.w = v.w > 0.f ? v.w : 0.01f * v.w;
            }
            *(float4*)(orow + tx * 8 + j) = v;
        }
    }
}

// ---------------- combine: gather expert outputs back to tokens -------------
__global__ void combine_kernel(int m) {
    int gw = (blockIdx.x * blockDim.x + threadIdx.x) >> 5;
    int lane = threadIdx.x & 31;
    if (gw >= S_TOK) return;
    int s = gw;
    float c1 = g_c1[s], c2 = g_c2[s];
    int d1 = g_d1[s], d2 = g_d2[s];
    float4 o0 = {0.f, 0.f, 0.f, 0.f}, o1 = {0.f, 0.f, 0.f, 0.f};
    if (d1 >= 0) {
        const float4* r = (const float4*)(g_eo + (size_t)d1 * CDIM);
        float4 a = r[lane], b = r[lane + 32];
        o0.x += c1 * a.x; o0.y += c1 * a.y; o0.z += c1 * a.z; o0.w += c1 * a.w;
        o1.x += c1 * b.x; o1.y += c1 * b.y; o1.z += c1 * b.z; o1.w += c1 * b.w;
    }
    if (d2 >= 0) {
        const float4* r = (const float4*)(g_eo + (size_t)d2 * CDIM);
        float4 a = r[lane], b = r[lane + 32];
        o0.x += c2 * a.x; o0.y += c2 * a.y; o0.z += c2 * a.z; o0.w += c2 * a.w;
        o1.x += c2 * b.x; o1.y += c2 * b.y; o1.z += c2 * b.z; o1.w += c2 * b.w;
    }
    float4* y = (float4*)((m == 0 ? g_y0 : g_y1) + (size_t)s * CDIM);
    y[lane] = o0; y[lane + 32] = o1;
}

// ---------------- fusion gate: a0 = sigmoid(av_c - av_s) per token ----------
__global__ void gatecoef_kernel(const float* __restrict__ gcw, const float* __restrict__ gcb,
                                const float* __restrict__ gsw, const float* __restrict__ gsb) {
    int gw = (blockIdx.x * blockDim.x + threadIdx.x) >> 5;
    int lane = threadIdx.x & 31;
    if (gw >= S_TOK) return;
    int s = gw;
    const float* ch = g_y0 + (size_t)s * CDIM;
    const float* sp = g_y1 + (size_t)s * CDIM;
    float vc = 0.f, vs = 0.f;
    for (int k = lane; k < CDIM; k += 32) {
        float a = ch[k], b = sp[k];
        vc += a * gcw[k] + b * gcw[CDIM + k];
        vs += a * gsw[k] + b * gsw[CDIM + k];
    }
#pragma unroll
    for (int o = 16; o > 0; o >>= 1) {
        vc += __shfl_xor_sync(0xffffffffu, vc, o);
        vs += __shfl_xor_sync(0xffffffffu, vs, o);
    }
    if (lane == 0) {
        float d = (vs + gsb[0]) - (vc + gcb[0]);
        g_a0[s] = 1.f / (1.f + expf(d));
    }
}

// ---------------- final output (token-major -> channel-major transpose) -----
__global__ void output_kernel(float* __restrict__ out) {
    __shared__ float sm[32][33];
    int b = blockIdx.x, c0 = blockIdx.y * 32, hw0 = blockIdx.z * 32;
    int tx = threadIdx.x, ty = threadIdx.y;
    int s = b * 4096 + hw0 + ty;
    float a0 = g_a0[s];
    float chv = g_y0[(size_t)s * CDIM + c0 + tx];
    float spv = g_y1[(size_t)s * CDIM + c0 + tx];
    sm[tx][ty] = a0 * chv + (1.f - a0) * spv;
    __syncthreads();
    out[((size_t)(b * CDIM + c0 + ty)) * 4096 + hw0 + tx] = sm[ty][tx];
}

__global__ void write_loss_kernel(float* __restrict__ out, int n) {
    float l = (g_loss[0] + g_loss[1]) * 0.5f;
    for (int i = threadIdx.x; i < n; i += blockDim.x) out[i] = l;
}

// ---------------- launch ----------------------------------------------------
extern "C" void kernel_launch(void* const* d_in, const int* in_sizes, int n_in,
                              void* d_out, int out_size) {
    const float* x      = (const float*)d_in[0];
    const float* audio  = (const float*)d_in[1];
    const float* wg_c   = (const float*)d_in[2];
    const float* w1_c   = (const float*)d_in[3];
    const float* b1_c   = (const float*)d_in[4];
    const float* w2_c   = (const float*)d_in[5];
    const float* b2_c   = (const float*)d_in[6];
    const float* wg_s   = (const float*)d_in[7];
    const float* w1_s   = (const float*)d_in[8];
    const float* b1_s   = (const float*)d_in[9];
    const float* w2_s   = (const float*)d_in[10];
    const float* b2_s   = (const float*)d_in[11];
    const float* gate_c_w = (const float*)d_in[12];
    const float* gate_c_b = (const float*)d_in[13];
    const float* gate_s_w = (const float*)d_in[14];
    const float* gate_s_b = (const float*)d_in[15];
    float* out = (float*)d_out;

    build_t_kernel<<<dim3(8, 8, 128), dim3(32, 32)>>>(x, audio);

    const int warp_blocks = (S_TOK * 32) / 256;  // 4096

    for (int m = 0; m < 2; m++) {
        const float* wg = m == 0 ? wg_c : wg_s;
        const float* w1 = m == 0 ? w1_c : w1_s;
        const float* b1 = m == 0 ? b1_c : b1_s;
        const float* w2 = m == 0 ? w2_c : w2_s;
        const float* b2 = m == 0 ? b2_c : b2_s;
        zero16_kernel<<<1, 32>>>();
        route_kernel<<<S_TOK / 16, 256>>>(wg);
        scan_kernel<<<1, 512>>>();
        loss_partial_kernel<<<1, 32>>>(m);
        scatter_kernel<<<warp_blocks, 256>>>();
        gemm_kernel<CDIM, HID, true><<<dim3(HID / 128, CAP / 128, NEXP), 256>>>(w1, b1);
        gemm_kernel<HID, CDIM, false><<<dim3(CDIM / 128, CAP / 128, NEXP), 256>>>(w2, b2);
        combine_kernel<<<warp_blocks, 256>>>(m);
    }

    gatecoef_kernel<<<warp_blocks, 256>>>(gate_c_w, gate_c_b, gate_s_w, gate_s_b);
    output_kernel<<<dim3(8, 8, 128), dim3(32, 32)>>>(out);
    if (out_size > NPIX) {
        write_loss_kernel<<<1, 256>>>(out + NPIX, out_size - NPIX);
    }
}

// round 13
// speedup vs baseline: 1.3103x; 1.3103x over previous
#include <cuda_runtime.h>
#include <cuda_bf16.h>
#include <cstdint>
#include <math.h>

#define S_TOK 32768
#define CDIM 256
#define NEXP 16
#define HID 1024
#define CAP 4096
#define NPIX (8*256*64*64)
#define NCHUNK 2048        // 16 tokens per chunk

// ---------------- scratch (device globals; no allocs allowed) ----------------
__device__ float g_t[S_TOK * CDIM];           // tokens [S,256]
__device__ float g_buf[NEXP * CAP * CDIM];    // dispatched expert input
__device__ float g_h[NEXP * CAP * HID];       // hidden
__device__ float g_eo[NEXP * CAP * CDIM];     // expert output
__device__ float g_y0[S_TOK * CDIM];          // channel MoE combined
__device__ float g_y1[S_TOK * CDIM];          // spatial MoE combined
__device__ int   g_idx1[S_TOK], g_idx2[S_TOK];
__device__ float g_gate1[S_TOK], g_gate2[S_TOK];
__device__ unsigned char g_keep2a[S_TOK];
__device__ float g_c1[S_TOK], g_c2[S_TOK];
__device__ int   g_d1[S_TOK], g_d2[S_TOK];
__device__ float g_probsum[NEXP];
__device__ int   g_tot1[NEXP];
__device__ int   g_cnt[NEXP];
__device__ float g_a0[S_TOK];
__device__ float g_loss[2];
__device__ int   g_ccnt1[NCHUNK * NEXP], g_ccnt2[NCHUNK * NEXP];   // per-chunk counts
__device__ int   g_cbase1[NCHUNK * NEXP], g_cbase2[NCHUNK * NEXP]; // exclusive bases

// ---------------- token build: t[s,c] = x[b,c,h,w] + audio[b,c] -------------
__global__ void build_t_kernel(const float* __restrict__ x,
                               const float* __restrict__ audio) {
    __shared__ float sm[32][33];
    int b = blockIdx.x, c0 = blockIdx.y * 32, hw0 = blockIdx.z * 32;
    int tx = threadIdx.x, ty = threadIdx.y;
    sm[ty][tx] = x[((size_t)(b * CDIM + c0 + ty)) * 4096 + hw0 + tx];
    __syncthreads();
    int c = c0 + tx;
    g_t[((size_t)(b * 4096 + hw0 + ty)) * CDIM + c] = __fadd_rn(sm[tx][ty], audio[b * CDIM + c]);
}

__global__ void zero16_kernel() {
    if (threadIdx.x < NEXP) g_probsum[threadIdx.x] = 0.f;
}

// ---------------- routing (FROZEN — bit-matches the reference) --------------
// logits: cublas gemv realization — 32 lane-partials, each serial FMA over
// stride-32 elements, combined by shfl_down-order tree (16,8,4,2,1).
__global__ void route_kernel(const float* __restrict__ wg) {
    __shared__ float wgs[NEXP][CDIM + 1];
    __shared__ float ts[16][CDIM];
    __shared__ float lg[16][NEXP];
    __shared__ float pr[16][NEXP];
    int tid = threadIdx.x;                 // 256
    int e = tid & 15, tok = tid >> 4;
    for (int i = tid; i < CDIM * NEXP; i += 256) wgs[i & 15][i >> 4] = wg[i];
    int s0 = blockIdx.x * 16;
    for (int i = tid; i < 16 * CDIM; i += 256)
        ts[i >> 8][i & 255] = g_t[(size_t)(s0 + (i >> 8)) * CDIM + (i & 255)];
    __syncthreads();

    float part[32];
#pragma unroll
    for (int j = 0; j < 32; j++) {
        float a = 0.f;
#pragma unroll
        for (int i = 0; i < 8; i++) {
            int c = j + 32 * i;
            a = __fmaf_rn(ts[tok][c], wgs[e][c], a);
        }
        part[j] = a;
    }
#pragma unroll
    for (int off = 16; off > 0; off >>= 1)
#pragma unroll
        for (int j = 0; j < 16; j++)
            if (j < off) part[j] = __fadd_rn(part[j], part[j + off]);
    lg[tok][e] = part[0];
    __syncthreads();

    if (e == 0) {
        float l[NEXP];
        float m = -INFINITY;
        for (int j = 0; j < NEXP; j++) { l[j] = lg[tok][j]; m = fmaxf(m, l[j]); }
        float ex[NEXP];
        float sum = 0.f;
        for (int j = 0; j < NEXP; j++) {
            ex[j] = expf(__fsub_rn(l[j], m));
            sum = __fadd_rn(sum, ex[j]);
        }
        float p[NEXP];
        int i1 = 0; float b1 = -1.f;
        for (int j = 0; j < NEXP; j++) {
            p[j] = __fdiv_rn(ex[j], sum);
            pr[tok][j] = p[j];
            if (p[j] > b1) { b1 = p[j]; i1 = j; }
        }
        int i2 = -1; float b2 = -2.f;
        for (int j = 0; j < NEXP; j++) {
            if (j == i1) continue;
            if (p[j] > b2) { b2 = p[j]; i2 = j; }
        }
        int s = s0 + tok;
        g_idx1[s] = i1; g_idx2[s] = i2;
        g_gate1[s] = p[i1]; g_gate2[s] = p[i2];
        g_keep2a[s] = (p[i2] > 0.2f) ? 1 : 0;
    }
    __syncthreads();
    if (tok == 0) {
        float a = 0.f;
        for (int j = 0; j < 16; j++) a += pr[j][e];
        atomicAdd(&g_probsum[e], a);
    }
}

// ---------------- phase 1: per-chunk expert counts (16 blocks x 128) --------
__global__ void count_kernel() {
    __shared__ short c1s[128 * NEXP];
    __shared__ short c2s[128 * NEXP];
    int tid = threadIdx.x;
    int chunk = blockIdx.x * 128 + tid;
#pragma unroll
    for (int e = 0; e < NEXP; e++) { c1s[tid * NEXP + e] = 0; c2s[tid * NEXP + e] = 0; }
    int s0 = chunk * 16;
    for (int i = 0; i < 16; i++) {
        int s = s0 + i;
        c1s[tid * NEXP + g_idx1[s]]++;
        if (g_keep2a[s]) c2s[tid * NEXP + g_idx2[s]]++;
    }
#pragma unroll
    for (int e = 0; e < NEXP; e++) {
        g_ccnt1[chunk * NEXP + e] = c1s[tid * NEXP + e];
        g_ccnt2[chunk * NEXP + e] = c2s[tid * NEXP + e];
    }
}

// ---------------- phase 2: exclusive prefix over chunks + totals + loss -----
__global__ void scan_chunks_kernel(int m) {
    __shared__ int tot1s[NEXP];
    int t = threadIdx.x;  // 512: warp w = expert w
    int w = t >> 5, lane = t & 31;
    int carry1 = 0, carry2 = 0;
    for (int it = 0; it < NCHUNK / 32; it++) {
        int chunk = it * 32 + lane;
        int v1 = g_ccnt1[chunk * NEXP + w], v2 = g_ccnt2[chunk * NEXP + w];
        int s1 = v1, s2 = v2;
#pragma unroll
        for (int o = 1; o < 32; o <<= 1) {
            int n1 = __shfl_up_sync(0xffffffffu, s1, o);
            int n2 = __shfl_up_sync(0xffffffffu, s2, o);
            if (lane >= o) { s1 += n1; s2 += n2; }
        }
        g_cbase1[chunk * NEXP + w] = s1 - v1 + carry1;
        g_cbase2[chunk * NEXP + w] = s2 - v2 + carry2;
        carry1 += __shfl_sync(0xffffffffu, s1, 31);
        carry2 += __shfl_sync(0xffffffffu, s2, 31);
    }
    if (lane == 31) {
        tot1s[w] = carry1;
        g_tot1[w] = carry1;
        int used = carry1 + carry2;
        g_cnt[w] = used > CAP ? CAP : used;
    }
    __syncthreads();
    if (t == 0) {
        float l = 0.f;
        for (int e = 0; e < NEXP; e++)
            l += ((float)tot1s[e] / (float)S_TOK) * (g_probsum[e] / (float)S_TOK);
        g_loss[m] = l * (float)NEXP * 0.01f;
    }
}

// ---------------- phase 3: per-token positions/coefs (16 blocks x 128) ------
__global__ void apply_kernel() {
    __shared__ int c1s[128 * NEXP];
    __shared__ int c2s[128 * NEXP];
    int tid = threadIdx.x;
    int chunk = blockIdx.x * 128 + tid;
#pragma unroll
    for (int e = 0; e < NEXP; e++) {
        c1s[tid * NEXP + e] = g_cbase1[chunk * NEXP + e];
        c2s[tid * NEXP + e] = g_cbase2[chunk * NEXP + e];
    }
    int s0 = chunk * 16;
    for (int i = 0; i < 16; i++) {
        int s = s0 + i;
        int e1 = g_idx1[s];
        int pos1 = c1s[tid * NEXP + e1]++;
        int e2 = g_idx2[s];
        int k2a = (int)g_keep2a[s];
        int pos2 = 0;
        if (k2a) pos2 = c2s[tid * NEXP + e2]++ + g_tot1[e2];
        int keep1 = (pos1 < CAP);
        int keep2 = k2a && (pos2 < CAP);
        float gate1 = g_gate1[s], gate2 = g_gate2[s];
        float denom = __fadd_rn(__fadd_rn(gate1, __fmul_rn(gate2, (float)k2a)), 1e-9f);
        g_c1[s] = keep1 ? __fdiv_rn(gate1, denom) : 0.f;
        g_c2[s] = keep2 ? __fdiv_rn(gate2, denom) : 0.f;
        g_d1[s] = keep1 ? (e1 * CAP + pos1) : -1;
        g_d2[s] = keep2 ? (e2 * CAP + pos2) : -1;
    }
}

// ---------------- dispatch: scatter token rows into expert buffers ----------
__global__ void scatter_kernel() {
    int gw = (blockIdx.x * blockDim.x + threadIdx.x) >> 5;
    int lane = threadIdx.x & 31;
    if (gw >= S_TOK) return;
    int s = gw;
    const float4* trow = (const float4*)(g_t + (size_t)s * CDIM);
    float4 v0 = trow[lane], v1 = trow[lane + 32];
    int d1 = g_d1[s], d2 = g_d2[s];
    if (d1 >= 0) {
        float4* o = (float4*)(g_buf + (size_t)d1 * CDIM);
        o[lane] = v0; o[lane + 32] = v1;
    }
    if (d2 >= 0) {
        float4* o = (float4*)(g_buf + (size_t)d2 * CDIM);
        o[lane] = v0; o[lane + 32] = v1;
    }
}

// ---------------- tiled SGEMM: 128x128 tile, 8x8/thread, double-buffered ----
template<int KDIM, int NDIM, bool PHASE1>
__global__ void __launch_bounds__(256)
gemm_kernel(const float* __restrict__ Bw, const float* __restrict__ bias) {
    const int e = blockIdx.z;
    if ((int)(blockIdx.y * 128) >= g_cnt[e]) return;   // skip empty row tiles
    const float* A = (PHASE1 ? g_buf : g_h) + (size_t)e * CAP * KDIM + (size_t)blockIdx.y * 128 * KDIM;
    const float* B = Bw + (size_t)e * KDIM * NDIM + blockIdx.x * 128;
    float* Cp = (PHASE1 ? g_h : g_eo) + (size_t)e * CAP * NDIM
              + (size_t)blockIdx.y * 128 * NDIM + blockIdx.x * 128;
    __shared__ float As[2][16][132];
    __shared__ float Bs[2][16][128];
    int tid = threadIdx.x;
    int ty = tid >> 4, tx = tid & 15;
    int ar = tid >> 2, ak = (tid & 3) * 4;
    int br = tid >> 5, bc = (tid & 31) * 4;
    float acc[8][8];
#pragma unroll
    for (int i = 0; i < 8; i++)
#pragma unroll
        for (int j = 0; j < 8; j++) acc[i][j] = 0.f;

    // preload k-tile 0
    {
        float4 a0 = *(const float4*)(A + (size_t)ar * KDIM + ak);
        float4 a1 = *(const float4*)(A + (size_t)(ar + 64) * KDIM + ak);
        As[0][ak + 0][ar] = a0.x; As[0][ak + 1][ar] = a0.y; As[0][ak + 2][ar] = a0.z; As[0][ak + 3][ar] = a0.w;
        As[0][ak + 0][ar + 64] = a1.x; As[0][ak + 1][ar + 64] = a1.y; As[0][ak + 2][ar + 64] = a1.z; As[0][ak + 3][ar + 64] = a1.w;
        *(float4*)(&Bs[0][br][bc])     = *(const float4*)(B + (size_t)br * NDIM + bc);
        *(float4*)(&Bs[0][br + 8][bc]) = *(const float4*)(B + (size_t)(br + 8) * NDIM + bc);
    }
    __syncthreads();

    int buf = 0;
    for (int k0 = 0; k0 < KDIM; k0 += 16) {
        float4 na0, na1, nb0, nb1;
        const bool has_next = (k0 + 16 < KDIM);
        if (has_next) {
            na0 = *(const float4*)(A + (size_t)ar * KDIM + k0 + 16 + ak);
            na1 = *(const float4*)(A + (size_t)(ar + 64) * KDIM + k0 + 16 + ak);
            nb0 = *(const float4*)(B + (size_t)(k0 + 16 + br) * NDIM + bc);
            nb1 = *(const float4*)(B + (size_t)(k0 + 16 + br + 8) * NDIM + bc);
        }
#pragma unroll
        for (int kk = 0; kk < 16; kk++) {
            float a[8], b[8];
#pragma unroll
            for (int i = 0; i < 8; i++) a[i] = As[buf][kk][ty * 8 + i];
#pragma unroll
            for (int j = 0; j < 8; j++) b[j] = Bs[buf][kk][tx * 8 + j];
#pragma unroll
            for (int i = 0; i < 8; i++)
#pragma unroll
                for (int j = 0; j < 8; j++) acc[i][j] += a[i] * b[j];
        }
        if (has_next) {
            int nb = buf ^ 1;
            As[nb][ak + 0][ar] = na0.x; As[nb][ak + 1][ar] = na0.y; As[nb][ak + 2][ar] = na0.z; As[nb][ak + 3][ar] = na0.w;
            As[nb][ak + 0][ar + 64] = na1.x; As[nb][ak + 1][ar + 64] = na1.y; As[nb][ak + 2][ar + 64] = na1.z; As[nb][ak + 3][ar + 64] = na1.w;
            *(float4*)(&Bs[nb][br][bc])     = nb0;
            *(float4*)(&Bs[nb][br + 8][bc]) = nb1;
        }
        __syncthreads();
        buf ^= 1;
    }
    const float* bv = bias + e * NDIM + blockIdx.x * 128;
#pragma unroll
    for (int i = 0; i < 8; i++) {
        int row = ty * 8 + i;
        float* orow = Cp + (size_t)row * NDIM;
#pragma unroll
        for (int j = 0; j < 8; j += 4) {
            float4 v;
            v.x = acc[i][j + 0] + bv[tx * 8 + j + 0];
            v.y = acc[i][j + 1] + bv[tx * 8 + j + 1];
            v.z = acc[i][j + 2] + bv[tx * 8 + j + 2];
            v.w = acc[i][j + 3] + bv[tx * 8 + j + 3];
            if (PHASE1) {
                v.x = v.x > 0.f ? v.x : 0.01f * v.x;
                v.y = v.y > 0.f ? v.y : 0.01f * v.y;
                v.z = v.z > 0.f ? v.z : 0.01f * v.z;
                v.w = v.w > 0.f ? v.w : 0.01f * v.w;
            }
            *(float4*)(orow + tx * 8 + j) = v;
        }
    }
}

// ---------------- combine: gather expert outputs back to tokens -------------
__global__ void combine_kernel(int m) {
    int gw = (blockIdx.x * blockDim.x + threadIdx.x) >> 5;
    int lane = threadIdx.x & 31;
    if (gw >= S_TOK) return;
    int s = gw;
    float c1 = g_c1[s], c2 = g_c2[s];
    int d1 = g_d1[s], d2 = g_d2[s];
    float4 o0 = {0.f, 0.f, 0.f, 0.f}, o1 = {0.f, 0.f, 0.f, 0.f};
    if (d1 >= 0) {
        const float4* r = (const float4*)(g_eo + (size_t)d1 * CDIM);
        float4 a = r[lane], b = r[lane + 32];
        o0.x += c1 * a.x; o0.y += c1 * a.y; o0.z += c1 * a.z; o0.w += c1 * a.w;
        o1.x += c1 * b.x; o1.y += c1 * b.y; o1.z += c1 * b.z; o1.w += c1 * b.w;
    }
    if (d2 >= 0) {
        const float4* r = (const float4*)(g_eo + (size_t)d2 * CDIM);
        float4 a = r[lane], b = r[lane + 32];
        o0.x += c2 * a.x; o0.y += c2 * a.y; o0.z += c2 * a.z; o0.w += c2 * a.w;
        o1.x += c2 * b.x; o1.y += c2 * b.y; o1.z += c2 * b.z; o1.w += c2 * b.w;
    }
    float4* y = (float4*)((m == 0 ? g_y0 : g_y1) + (size_t)s * CDIM);
    y[lane] = o0; y[lane + 32] = o1;
}

// ---------------- fusion gate: a0 = sigmoid(av_c - av_s) per token ----------
__global__ void gatecoef_kernel(const float* __restrict__ gcw, const float* __restrict__ gcb,
                                const float* __restrict__ gsw, const float* __restrict__ gsb) {
    int gw = (blockIdx.x * blockDim.x + threadIdx.x) >> 5;
    int lane = threadIdx.x & 31;
    if (gw >= S_TOK) return;
    int s = gw;
    const float* ch = g_y0 + (size_t)s * CDIM;
    const float* sp = g_y1 + (size_t)s * CDIM;
    float vc = 0.f, vs = 0.f;
    for (int k = lane; k < CDIM; k += 32) {
        float a = ch[k], b = sp[k];
        vc += a * gcw[k] + b * gcw[CDIM + k];
        vs += a * gsw[k] + b * gsw[CDIM + k];
    }
#pragma unroll
    for (int o = 16; o > 0; o >>= 1) {
        vc += __shfl_xor_sync(0xffffffffu, vc, o);
        vs += __shfl_xor_sync(0xffffffffu, vs, o);
    }
    if (lane == 0) {
        float d = (vs + gsb[0]) - (vc + gcb[0]);
        g_a0[s] = 1.f / (1.f + expf(d));
    }
}

// ---------------- final output (token-major -> channel-major transpose) -----
__global__ void output_kernel(float* __restrict__ out) {
    __shared__ float sm[32][33];
    int b = blockIdx.x, c0 = blockIdx.y * 32, hw0 = blockIdx.z * 32;
    int tx = threadIdx.x, ty = threadIdx.y;
    int s = b * 4096 + hw0 + ty;
    float a0 = g_a0[s];
    float chv = g_y0[(size_t)s * CDIM + c0 + tx];
    float spv = g_y1[(size_t)s * CDIM + c0 + tx];
    sm[tx][ty] = a0 * chv + (1.f - a0) * spv;
    __syncthreads();
    out[((size_t)(b * CDIM + c0 + ty)) * 4096 + hw0 + tx] = sm[ty][tx];
}

__global__ void write_loss_kernel(float* __restrict__ out, int n) {
    float l = (g_loss[0] + g_loss[1]) * 0.5f;
    for (int i = threadIdx.x; i < n; i += blockDim.x) out[i] = l;
}

// ---------------- launch ----------------------------------------------------
extern "C" void kernel_launch(void* const* d_in, const int* in_sizes, int n_in,
                              void* d_out, int out_size) {
    const float* x      = (const float*)d_in[0];
    const float* audio  = (const float*)d_in[1];
    const float* wg_c   = (const float*)d_in[2];
    const float* w1_c   = (const float*)d_in[3];
    const float* b1_c   = (const float*)d_in[4];
    const float* w2_c   = (const float*)d_in[5];
    const float* b2_c   = (const float*)d_in[6];
    const float* wg_s   = (const float*)d_in[7];
    const float* w1_s   = (const float*)d_in[8];
    const float* b1_s   = (const float*)d_in[9];
    const float* w2_s   = (const float*)d_in[10];
    const float* b2_s   = (const float*)d_in[11];
    const float* gate_c_w = (const float*)d_in[12];
    const float* gate_c_b = (const float*)d_in[13];
    const float* gate_s_w = (const float*)d_in[14];
    const float* gate_s_b = (const float*)d_in[15];
    float* out = (float*)d_out;

    build_t_kernel<<<dim3(8, 8, 128), dim3(32, 32)>>>(x, audio);

    const int warp_blocks = (S_TOK * 32) / 256;  // 4096

    for (int m = 0; m < 2; m++) {
        const float* wg = m == 0 ? wg_c : wg_s;
        const float* w1 = m == 0 ? w1_c : w1_s;
        const float* b1 = m == 0 ? b1_c : b1_s;
        const float* w2 = m == 0 ? w2_c : w2_s;
        const float* b2 = m == 0 ? b2_c : b2_s;
        zero16_kernel<<<1, 32>>>();
        route_kernel<<<S_TOK / 16, 256>>>(wg);
        count_kernel<<<NCHUNK / 128, 128>>>();
        scan_chunks_kernel<<<1, 512>>>(m);
        apply_kernel<<<NCHUNK / 128, 128>>>();
        scatter_kernel<<<warp_blocks, 256>>>();
        gemm_kernel<CDIM, HID, true><<<dim3(HID / 128, CAP / 128, NEXP), 256>>>(w1, b1);
        gemm_kernel<HID, CDIM, false><<<dim3(CDIM / 128, CAP / 128, NEXP), 256>>>(w2, b2);
        combine_kernel<<<warp_blocks, 256>>>(m);
    }

    gatecoef_kernel<<<warp_blocks, 256>>>(gate_c_w, gate_c_b, gate_s_w, gate_s_b);
    output_kernel<<<dim3(8, 8, 128), dim3(32, 32)>>>(out);
    if (out_size > NPIX) {
        write_loss_kernel<<<1, 256>>>(out + NPIX, out_size - NPIX);
    }
}

// round 14
// speedup vs baseline: 1.4624x; 1.1161x over previous
#include <cuda_runtime.h>
#include <cuda_bf16.h>
#include <cstdint>
#include <math.h>

#define S_TOK 32768
#define CDIM 256
#define NEXP 16
#define HID 1024
#define CAP 4096
#define NPIX (8*256*64*64)
#define NCHUNK 2048        // 16 tokens per chunk

// ---------------- scratch (device globals; no allocs allowed) ----------------
__device__ float g_t[S_TOK * CDIM];           // tokens [S,256]
__device__ float g_buf[NEXP * CAP * CDIM];    // dispatched expert input
__device__ float g_h[NEXP * CAP * HID];       // hidden
__device__ float g_eo[NEXP * CAP * CDIM];     // expert output
__device__ float g_y0[S_TOK * CDIM];          // channel MoE combined
__device__ float g_y1[S_TOK * CDIM];          // spatial MoE combined
__device__ int   g_idx1[S_TOK], g_idx2[S_TOK];
__device__ float g_gate1[S_TOK], g_gate2[S_TOK];
__device__ unsigned char g_keep2a[S_TOK];
__device__ float g_c1[S_TOK], g_c2[S_TOK];
__device__ int   g_d1[S_TOK], g_d2[S_TOK];
__device__ float g_probsum[NEXP];
__device__ int   g_tot1[NEXP];
__device__ int   g_cnt[NEXP];
__device__ float g_a0[S_TOK];
__device__ float g_loss[2];
__device__ int   g_ccnt1[NCHUNK * NEXP], g_ccnt2[NCHUNK * NEXP];
__device__ int   g_cbase1[NCHUNK * NEXP], g_cbase2[NCHUNK * NEXP];

// TF32 split helpers (cutlass 3xTF32 scheme)
__device__ __forceinline__ float tf32_rna(float x) {
    uint32_t u;
    asm("cvt.rna.tf32.f32 %0, %1;" : "=r"(u) : "f"(x));
    return __uint_as_float(u);
}
__device__ __forceinline__ void mma_tf32(float c[4], float a0, float a1, float a2, float a3,
                                         float b0, float b1) {
    asm volatile(
        "mma.sync.aligned.m16n8k8.row.col.f32.tf32.tf32.f32 "
        "{%0,%1,%2,%3},{%4,%5,%6,%7},{%8,%9},{%0,%1,%2,%3};"
        : "+f"(c[0]), "+f"(c[1]), "+f"(c[2]), "+f"(c[3])
        : "r"(__float_as_uint(a0)), "r"(__float_as_uint(a1)),
          "r"(__float_as_uint(a2)), "r"(__float_as_uint(a3)),
          "r"(__float_as_uint(b0)), "r"(__float_as_uint(b1)));
}

// ---------------- token build: t[s,c] = x[b,c,h,w] + audio[b,c] -------------
__global__ void build_t_kernel(const float* __restrict__ x,
                               const float* __restrict__ audio) {
    __shared__ float sm[32][33];
    int b = blockIdx.x, c0 = blockIdx.y * 32, hw0 = blockIdx.z * 32;
    int tx = threadIdx.x, ty = threadIdx.y;
    sm[ty][tx] = x[((size_t)(b * CDIM + c0 + ty)) * 4096 + hw0 + tx];
    __syncthreads();
    int c = c0 + tx;
    g_t[((size_t)(b * 4096 + hw0 + ty)) * CDIM + c] = __fadd_rn(sm[tx][ty], audio[b * CDIM + c]);
}

__global__ void zero16_kernel() {
    if (threadIdx.x < NEXP) g_probsum[threadIdx.x] = 0.f;
}

// ---------------- routing (FROZEN — bit-matches the reference) --------------
__global__ void route_kernel(const float* __restrict__ wg) {
    __shared__ float wgs[NEXP][CDIM + 1];
    __shared__ float ts[16][CDIM];
    __shared__ float lg[16][NEXP];
    __shared__ float pr[16][NEXP];
    int tid = threadIdx.x;                 // 256
    int e = tid & 15, tok = tid >> 4;
    for (int i = tid; i < CDIM * NEXP; i += 256) wgs[i & 15][i >> 4] = wg[i];
    int s0 = blockIdx.x * 16;
    for (int i = tid; i < 16 * CDIM; i += 256)
        ts[i >> 8][i & 255] = g_t[(size_t)(s0 + (i >> 8)) * CDIM + (i & 255)];
    __syncthreads();

    float part[32];
#pragma unroll
    for (int j = 0; j < 32; j++) {
        float a = 0.f;
#pragma unroll
        for (int i = 0; i < 8; i++) {
            int c = j + 32 * i;
            a = __fmaf_rn(ts[tok][c], wgs[e][c], a);
        }
        part[j] = a;
    }
#pragma unroll
    for (int off = 16; off > 0; off >>= 1)
#pragma unroll
        for (int j = 0; j < 16; j++)
            if (j < off) part[j] = __fadd_rn(part[j], part[j + off]);
    lg[tok][e] = part[0];
    __syncthreads();

    if (e == 0) {
        float l[NEXP];
        float m = -INFINITY;
        for (int j = 0; j < NEXP; j++) { l[j] = lg[tok][j]; m = fmaxf(m, l[j]); }
        float ex[NEXP];
        float sum = 0.f;
        for (int j = 0; j < NEXP; j++) {
            ex[j] = expf(__fsub_rn(l[j], m));
            sum = __fadd_rn(sum, ex[j]);
        }
        float p[NEXP];
        int i1 = 0; float b1 = -1.f;
        for (int j = 0; j < NEXP; j++) {
            p[j] = __fdiv_rn(ex[j], sum);
            pr[tok][j] = p[j];
            if (p[j] > b1) { b1 = p[j]; i1 = j; }
        }
        int i2 = -1; float b2 = -2.f;
        for (int j = 0; j < NEXP; j++) {
            if (j == i1) continue;
            if (p[j] > b2) { b2 = p[j]; i2 = j; }
        }
        int s = s0 + tok;
        g_idx1[s] = i1; g_idx2[s] = i2;
        g_gate1[s] = p[i1]; g_gate2[s] = p[i2];
        g_keep2a[s] = (p[i2] > 0.2f) ? 1 : 0;
    }
    __syncthreads();
    if (tok == 0) {
        float a = 0.f;
        for (int j = 0; j < 16; j++) a += pr[j][e];
        atomicAdd(&g_probsum[e], a);
    }
}

// ---------------- phase 1: per-chunk expert counts --------------------------
__global__ void count_kernel() {
    __shared__ short c1s[128 * NEXP];
    __shared__ short c2s[128 * NEXP];
    int tid = threadIdx.x;
    int chunk = blockIdx.x * 128 + tid;
#pragma unroll
    for (int e = 0; e < NEXP; e++) { c1s[tid * NEXP + e] = 0; c2s[tid * NEXP + e] = 0; }
    int s0 = chunk * 16;
    for (int i = 0; i < 16; i++) {
        int s = s0 + i;
        c1s[tid * NEXP + g_idx1[s]]++;
        if (g_keep2a[s]) c2s[tid * NEXP + g_idx2[s]]++;
    }
#pragma unroll
    for (int e = 0; e < NEXP; e++) {
        g_ccnt1[chunk * NEXP + e] = c1s[tid * NEXP + e];
        g_ccnt2[chunk * NEXP + e] = c2s[tid * NEXP + e];
    }
}

// ---------------- phase 2: exclusive prefix over chunks + totals + loss -----
__global__ void scan_chunks_kernel(int m) {
    __shared__ int tot1s[NEXP];
    int t = threadIdx.x;  // 512: warp w = expert w
    int w = t >> 5, lane = t & 31;
    int carry1 = 0, carry2 = 0;
    for (int it = 0; it < NCHUNK / 32; it++) {
        int chunk = it * 32 + lane;
        int v1 = g_ccnt1[chunk * NEXP + w], v2 = g_ccnt2[chunk * NEXP + w];
        int s1 = v1, s2 = v2;
#pragma unroll
        for (int o = 1; o < 32; o <<= 1) {
            int n1 = __shfl_up_sync(0xffffffffu, s1, o);
            int n2 = __shfl_up_sync(0xffffffffu, s2, o);
            if (lane >= o) { s1 += n1; s2 += n2; }
        }
        g_cbase1[chunk * NEXP + w] = s1 - v1 + carry1;
        g_cbase2[chunk * NEXP + w] = s2 - v2 + carry2;
        carry1 += __shfl_sync(0xffffffffu, s1, 31);
        carry2 += __shfl_sync(0xffffffffu, s2, 31);
    }
    if (lane == 31) {
        tot1s[w] = carry1;
        g_tot1[w] = carry1;
        int used = carry1 + carry2;
        g_cnt[w] = used > CAP ? CAP : used;
    }
    __syncthreads();
    if (t == 0) {
        float l = 0.f;
        for (int e = 0; e < NEXP; e++)
            l += ((float)tot1s[e] / (float)S_TOK) * (g_probsum[e] / (float)S_TOK);
        g_loss[m] = l * (float)NEXP * 0.01f;
    }
}

// ---------------- phase 3: per-token positions/coefs ------------------------
__global__ void apply_kernel() {
    __shared__ int c1s[128 * NEXP];
    __shared__ int c2s[128 * NEXP];
    int tid = threadIdx.x;
    int chunk = blockIdx.x * 128 + tid;
#pragma unroll
    for (int e = 0; e < NEXP; e++) {
        c1s[tid * NEXP + e] = g_cbase1[chunk * NEXP + e];
        c2s[tid * NEXP + e] = g_cbase2[chunk * NEXP + e];
    }
    int s0 = chunk * 16;
    for (int i = 0; i < 16; i++) {
        int s = s0 + i;
        int e1 = g_idx1[s];
        int pos1 = c1s[tid * NEXP + e1]++;
        int e2 = g_idx2[s];
        int k2a = (int)g_keep2a[s];
        int pos2 = 0;
        if (k2a) pos2 = c2s[tid * NEXP + e2]++ + g_tot1[e2];
        int keep1 = (pos1 < CAP);
        int keep2 = k2a && (pos2 < CAP);
        float gate1 = g_gate1[s], gate2 = g_gate2[s];
        float denom = __fadd_rn(__fadd_rn(gate1, __fmul_rn(gate2, (float)k2a)), 1e-9f);
        g_c1[s] = keep1 ? __fdiv_rn(gate1, denom) : 0.f;
        g_c2[s] = keep2 ? __fdiv_rn(gate2, denom) : 0.f;
        g_d1[s] = keep1 ? (e1 * CAP + pos1) : -1;
        g_d2[s] = keep2 ? (e2 * CAP + pos2) : -1;
    }
}

// ---------------- dispatch: scatter token rows into expert buffers ----------
__global__ void scatter_kernel() {
    int gw = (blockIdx.x * blockDim.x + threadIdx.x) >> 5;
    int lane = threadIdx.x & 31;
    if (gw >= S_TOK) return;
    int s = gw;
    const float4* trow = (const float4*)(g_t + (size_t)s * CDIM);
    float4 v0 = trow[lane], v1 = trow[lane + 32];
    int d1 = g_d1[s], d2 = g_d2[s];
    if (d1 >= 0) {
        float4* o = (float4*)(g_buf + (size_t)d1 * CDIM);
        o[lane] = v0; o[lane + 32] = v1;
    }
    if (d2 >= 0) {
        float4* o = (float4*)(g_buf + (size_t)d2 * CDIM);
        o[lane] = v0; o[lane + 32] = v1;
    }
}

// ---------------- tensor-core GEMM: 3xTF32, 128x128 tile, m64n32/warp -------
// smem [k][dim] with stride 136 -> conflict-free fragment LDS.
template<int KDIM, int NDIM, bool PHASE1>
__global__ void __launch_bounds__(256)
gemm_tc_kernel(const float* __restrict__ Bw, const float* __restrict__ bias) {
    const int e = blockIdx.z;
    if ((int)(blockIdx.y * 128) >= g_cnt[e]) return;   // skip empty row tiles
    const float* A = (PHASE1 ? g_buf : g_h) + (size_t)e * CAP * KDIM + (size_t)blockIdx.y * 128 * KDIM;
    const float* B = Bw + (size_t)e * KDIM * NDIM + blockIdx.x * 128;
    float* Cp = (PHASE1 ? g_h : g_eo) + (size_t)e * CAP * NDIM
              + (size_t)blockIdx.y * 128 * NDIM + blockIdx.x * 128;
    __shared__ float As[2][8][136];
    __shared__ float Bs[2][8][136];
    int tid = threadIdx.x, lane = tid & 31, wid = tid >> 5;
    int wm = wid >> 2, wn = wid & 3;        // warp tile: m = wm*64, n = wn*32
    int am = tid >> 1;                      // 0..127 (A row)
    int ak = (tid & 1) * 4;                 // 0 or 4  (A k-quad)
    int bk = tid >> 5;                      // 0..7    (B k-row)
    int bn = (tid & 31) * 4;                // B n-quad

    float c[4][4][4];
#pragma unroll
    for (int mi = 0; mi < 4; mi++)
#pragma unroll
        for (int ni = 0; ni < 4; ni++)
#pragma unroll
            for (int q = 0; q < 4; q++) c[mi][ni][q] = 0.f;

    // preload k-tile 0
    {
        float4 a4 = *(const float4*)(A + (size_t)am * KDIM + ak);
        float4 b4 = *(const float4*)(B + (size_t)bk * NDIM + bn);
        As[0][ak + 0][am] = a4.x; As[0][ak + 1][am] = a4.y;
        As[0][ak + 2][am] = a4.z; As[0][ak + 3][am] = a4.w;
        *(float4*)(&Bs[0][bk][bn]) = b4;
    }
    __syncthreads();

    const int NT = KDIM / 8;
    int buf = 0;
    int r = lane >> 2, cq = lane & 3;       // A frag: row, k-col ; B frag: kr=cq, nc=r
    for (int t = 0; t < NT; t++) {
        float4 na, nb;
        const bool hn = (t + 1 < NT);
        if (hn) {
            na = *(const float4*)(A + (size_t)am * KDIM + (t + 1) * 8 + ak);
            nb = *(const float4*)(B + (size_t)((t + 1) * 8 + bk) * NDIM + bn);
        }
        // A fragments (4 m-tiles) + hi/lo split
        float ahi[4][4], alo[4][4];
#pragma unroll
        for (int mi = 0; mi < 4; mi++) {
            int mb = wm * 64 + mi * 16;
            float x0 = As[buf][cq][mb + r];
            float x1 = As[buf][cq][mb + r + 8];
            float x2 = As[buf][cq + 4][mb + r];
            float x3 = As[buf][cq + 4][mb + r + 8];
            ahi[mi][0] = tf32_rna(x0); alo[mi][0] = tf32_rna(x0 - ahi[mi][0]);
            ahi[mi][1] = tf32_rna(x1); alo[mi][1] = tf32_rna(x1 - ahi[mi][1]);
            ahi[mi][2] = tf32_rna(x2); alo[mi][2] = tf32_rna(x2 - ahi[mi][2]);
            ahi[mi][3] = tf32_rna(x3); alo[mi][3] = tf32_rna(x3 - ahi[mi][3]);
        }
        // B fragments (4 n-tiles) + hi/lo split
        float bhi[4][2], blo[4][2];
#pragma unroll
        for (int ni = 0; ni < 4; ni++) {
            int nb0 = wn * 32 + ni * 8;
            float y0 = Bs[buf][cq][nb0 + r];
            float y1 = Bs[buf][cq + 4][nb0 + r];
            bhi[ni][0] = tf32_rna(y0); blo[ni][0] = tf32_rna(y0 - bhi[ni][0]);
            bhi[ni][1] = tf32_rna(y1); blo[ni][1] = tf32_rna(y1 - bhi[ni][1]);
        }
        // 3xTF32 mma
#pragma unroll
        for (int mi = 0; mi < 4; mi++)
#pragma unroll
            for (int ni = 0; ni < 4; ni++) {
                mma_tf32(c[mi][ni], ahi[mi][0], ahi[mi][1], ahi[mi][2], ahi[mi][3],
                         blo[ni][0], blo[ni][1]);
                mma_tf32(c[mi][ni], alo[mi][0], alo[mi][1], alo[mi][2], alo[mi][3],
                         bhi[ni][0], bhi[ni][1]);
                mma_tf32(c[mi][ni], ahi[mi][0], ahi[mi][1], ahi[mi][2], ahi[mi][3],
                         bhi[ni][0], bhi[ni][1]);
            }
        if (hn) {
            int nbuf = buf ^ 1;
            As[nbuf][ak + 0][am] = na.x; As[nbuf][ak + 1][am] = na.y;
            As[nbuf][ak + 2][am] = na.z; As[nbuf][ak + 3][am] = na.w;
            *(float4*)(&Bs[nbuf][bk][bn]) = nb;
        }
        __syncthreads();
        buf ^= 1;
    }

    // epilogue: bias (+ leaky for phase1), direct stores
    const float* bv = bias + e * NDIM + blockIdx.x * 128;
    int cg = (lane & 3) * 2;
#pragma unroll
    for (int mi = 0; mi < 4; mi++) {
#pragma unroll
        for (int ni = 0; ni < 4; ni++) {
            int ml = wm * 64 + mi * 16 + r;
            int nl = wn * 32 + ni * 8 + cg;
            float bb0 = bv[nl], bb1 = bv[nl + 1];
            float v0 = c[mi][ni][0] + bb0;
            float v1 = c[mi][ni][1] + bb1;
            float v2 = c[mi][ni][2] + bb0;
            float v3 = c[mi][ni][3] + bb1;
            if (PHASE1) {
                v0 = v0 > 0.f ? v0 : 0.01f * v0;
                v1 = v1 > 0.f ? v1 : 0.01f * v1;
                v2 = v2 > 0.f ? v2 : 0.01f * v2;
                v3 = v3 > 0.f ? v3 : 0.01f * v3;
            }
            float2 p0 = {v0, v1}, p1 = {v2, v3};
            *(float2*)(Cp + (size_t)ml * NDIM + nl) = p0;
            *(float2*)(Cp + (size_t)(ml + 8) * NDIM + nl) = p1;
        }
    }
}

// ---------------- combine: gather expert outputs back to tokens -------------
__global__ void combine_kernel(int m) {
    int gw = (blockIdx.x * blockDim.x + threadIdx.x) >> 5;
    int lane = threadIdx.x & 31;
    if (gw >= S_TOK) return;
    int s = gw;
    float c1 = g_c1[s], c2 = g_c2[s];
    int d1 = g_d1[s], d2 = g_d2[s];
    float4 o0 = {0.f, 0.f, 0.f, 0.f}, o1 = {0.f, 0.f, 0.f, 0.f};
    if (d1 >= 0) {
        const float4* rr = (const float4*)(g_eo + (size_t)d1 * CDIM);
        float4 a = rr[lane], b = rr[lane + 32];
        o0.x += c1 * a.x; o0.y += c1 * a.y; o0.z += c1 * a.z; o0.w += c1 * a.w;
        o1.x += c1 * b.x; o1.y += c1 * b.y; o1.z += c1 * b.z; o1.w += c1 * b.w;
    }
    if (d2 >= 0) {
        const float4* rr = (const float4*)(g_eo + (size_t)d2 * CDIM);
        float4 a = rr[lane], b = rr[lane + 32];
        o0.x += c2 * a.x; o0.y += c2 * a.y; o0.z += c2 * a.z; o0.w += c2 * a.w;
        o1.x += c2 * b.x; o1.y += c2 * b.y; o1.z += c2 * b.z; o1.w += c2 * b.w;
    }
    float4* y = (float4*)((m == 0 ? g_y0 : g_y1) + (size_t)s * CDIM);
    y[lane] = o0; y[lane + 32] = o1;
}

// ---------------- fusion gate: a0 = sigmoid(av_c - av_s) per token ----------
__global__ void gatecoef_kernel(const float* __restrict__ gcw, const float* __restrict__ gcb,
                                const float* __restrict__ gsw, const float* __restrict__ gsb) {
    int gw = (blockIdx.x * blockDim.x + threadIdx.x) >> 5;
    int lane = threadIdx.x & 31;
    if (gw >= S_TOK) return;
    int s = gw;
    const float* ch = g_y0 + (size_t)s * CDIM;
    const float* sp = g_y1 + (size_t)s * CDIM;
    float vc = 0.f, vs = 0.f;
    for (int k = lane; k < CDIM; k += 32) {
        float a = ch[k], b = sp[k];
        vc += a * gcw[k] + b * gcw[CDIM + k];
        vs += a * gsw[k] + b * gsw[CDIM + k];
    }
#pragma unroll
    for (int o = 16; o > 0; o >>= 1) {
        vc += __shfl_xor_sync(0xffffffffu, vc, o);
        vs += __shfl_xor_sync(0xffffffffu, vs, o);
    }
    if (lane == 0) {
        float d = (vs + gsb[0]) - (vc + gcb[0]);
        g_a0[s] = 1.f / (1.f + expf(d));
    }
}

// ---------------- final output (token-major -> channel-major transpose) -----
__global__ void output_kernel(float* __restrict__ out) {
    __shared__ float sm[32][33];
    int b = blockIdx.x, c0 = blockIdx.y * 32, hw0 = blockIdx.z * 32;
    int tx = threadIdx.x, ty = threadIdx.y;
    int s = b * 4096 + hw0 + ty;
    float a0 = g_a0[s];
    float chv = g_y0[(size_t)s * CDIM + c0 + tx];
    float spv = g_y1[(size_t)s * CDIM + c0 + tx];
    sm[tx][ty] = a0 * chv + (1.f - a0) * spv;
    __syncthreads();
    out[((size_t)(b * CDIM + c0 + ty)) * 4096 + hw0 + tx] = sm[ty][tx];
}

__global__ void write_loss_kernel(float* __restrict__ out, int n) {
    float l = (g_loss[0] + g_loss[1]) * 0.5f;
    for (int i = threadIdx.x; i < n; i += blockDim.x) out[i] = l;
}

// ---------------- launch ----------------------------------------------------
extern "C" void kernel_launch(void* const* d_in, const int* in_sizes, int n_in,
                              void* d_out, int out_size) {
    const float* x      = (const float*)d_in[0];
    const float* audio  = (const float*)d_in[1];
    const float* wg_c   = (const float*)d_in[2];
    const float* w1_c   = (const float*)d_in[3];
    const float* b1_c   = (const float*)d_in[4];
    const float* w2_c   = (const float*)d_in[5];
    const float* b2_c   = (const float*)d_in[6];
    const float* wg_s   = (const float*)d_in[7];
    const float* w1_s   = (const float*)d_in[8];
    const float* b1_s   = (const float*)d_in[9];
    const float* w2_s   = (const float*)d_in[10];
    const float* b2_s   = (const float*)d_in[11];
    const float* gate_c_w = (const float*)d_in[12];
    const float* gate_c_b = (const float*)d_in[13];
    const float* gate_s_w = (const float*)d_in[14];
    const float* gate_s_b = (const float*)d_in[15];
    float* out = (float*)d_out;

    build_t_kernel<<<dim3(8, 8, 128), dim3(32, 32)>>>(x, audio);

    const int warp_blocks = (S_TOK * 32) / 256;  // 4096

    for (int m = 0; m < 2; m++) {
        const float* wg = m == 0 ? wg_c : wg_s;
        const float* w1 = m == 0 ? w1_c : w1_s;
        const float* b1 = m == 0 ? b1_c : b1_s;
        const float* w2 = m == 0 ? w2_c : w2_s;
        const float* b2 = m == 0 ? b2_c : b2_s;
        zero16_kernel<<<1, 32>>>();
        route_kernel<<<S_TOK / 16, 256>>>(wg);
        count_kernel<<<NCHUNK / 128, 128>>>();
        scan_chunks_kernel<<<1, 512>>>(m);
        apply_kernel<<<NCHUNK / 128, 128>>>();
        scatter_kernel<<<warp_blocks, 256>>>();
        gemm_tc_kernel<CDIM, HID, true><<<dim3(HID / 128, CAP / 128, NEXP), 256>>>(w1, b1);
        gemm_tc_kernel<HID, CDIM, false><<<dim3(CDIM / 128, CAP / 128, NEXP), 256>>>(w2, b2);
        combine_kernel<<<warp_blocks, 256>>>(m);
    }

    gatecoef_kernel<<<warp_blocks, 256>>>(gate_c_w, gate_c_b, gate_s_w, gate_s_b);
    output_kernel<<<dim3(8, 8, 128), dim3(32, 32)>>>(out);
    if (out_size > NPIX) {
        write_loss_kernel<<<1, 256>>>(out + NPIX, out_size - NPIX);
    }
}

// round 16
// speedup vs baseline: 2.0842x; 1.4252x over previous
#include <cuda_runtime.h>
#include <cuda_bf16.h>
#include <cstdint>
#include <math.h>

#define S_TOK 32768
#define CDIM 256
#define NEXP 16
#define HID 1024
#define CAP 4096
#define NPIX (8*256*64*64)
#define NCHUNK 2048        // 16 tokens per chunk

// ---------------- scratch (device globals; no allocs allowed) ----------------
__device__ float g_t[S_TOK * CDIM];
__device__ float g_buf[NEXP * CAP * CDIM];
__device__ float g_h[NEXP * CAP * HID];
__device__ float g_eo[NEXP * CAP * CDIM];
__device__ float g_y0[S_TOK * CDIM];
__device__ float g_y1[S_TOK * CDIM];
__device__ int   g_idx1[S_TOK], g_idx2[S_TOK];
__device__ float g_gate1[S_TOK], g_gate2[S_TOK];
__device__ unsigned char g_keep2a[S_TOK];
__device__ float g_c1[S_TOK], g_c2[S_TOK];
__device__ int   g_d1[S_TOK], g_d2[S_TOK];
__device__ float g_probsum[NEXP];
__device__ int   g_tot1[NEXP];
__device__ int   g_cnt[NEXP];
__device__ float g_a0[S_TOK];
__device__ float g_loss[2];
__device__ int   g_ccnt1[NCHUNK * NEXP], g_ccnt2[NCHUNK * NEXP];
__device__ int   g_cbase1[NCHUNK * NEXP], g_cbase2[NCHUNK * NEXP];

// ---------------- helpers ----------------------------------------------------
// bf16x2 split: x = hi + lo (each bf16). Packed pairs along k: low 16 bits = even k.
__device__ __forceinline__ void bf16x2_split(float x0, float x1, uint32_t& p_hi, uint32_t& p_lo) {
    __nv_bfloat16 h0 = __float2bfloat16_rn(x0);
    __nv_bfloat16 h1 = __float2bfloat16_rn(x1);
    float r0 = x0 - __bfloat162float(h0);
    float r1 = x1 - __bfloat162float(h1);
    __nv_bfloat16 l0 = __float2bfloat16_rn(r0);
    __nv_bfloat16 l1 = __float2bfloat16_rn(r1);
    p_hi = (uint32_t)__bfloat16_as_ushort(h0) | ((uint32_t)__bfloat16_as_ushort(h1) << 16);
    p_lo = (uint32_t)__bfloat16_as_ushort(l0) | ((uint32_t)__bfloat16_as_ushort(l1) << 16);
}
__device__ __forceinline__ void mma_bf16(float c[4], uint32_t a0, uint32_t a1, uint32_t a2, uint32_t a3,
                                         uint32_t b0, uint32_t b1) {
    asm volatile(
        "mma.sync.aligned.m16n8k16.row.col.f32.bf16.bf16.f32 "
        "{%0,%1,%2,%3},{%4,%5,%6,%7},{%8,%9},{%0,%1,%2,%3};"
        : "+f"(c[0]), "+f"(c[1]), "+f"(c[2]), "+f"(c[3])
        : "r"(a0), "r"(a1), "r"(a2), "r"(a3), "r"(b0), "r"(b1));
}

// ---------------- token build -----------------------------------------------
__global__ void build_t_kernel(const float* __restrict__ x,
                               const float* __restrict__ audio) {
    __shared__ float sm[32][33];
    int b = blockIdx.x, c0 = blockIdx.y * 32, hw0 = blockIdx.z * 32;
    int tx = threadIdx.x, ty = threadIdx.y;
    sm[ty][tx] = x[((size_t)(b * CDIM + c0 + ty)) * 4096 + hw0 + tx];
    __syncthreads();
    int c = c0 + tx;
    g_t[((size_t)(b * 4096 + hw0 + ty)) * CDIM + c] = __fadd_rn(sm[tx][ty], audio[b * CDIM + c]);
}

__global__ void zero16_kernel() {
    if (threadIdx.x < NEXP) g_probsum[threadIdx.x] = 0.f;
}

// ---------------- routing (FROZEN — bit-matches the reference) --------------
__global__ void route_kernel(const float* __restrict__ wg) {
    __shared__ float wgs[NEXP][CDIM + 1];
    __shared__ float ts[16][CDIM];
    __shared__ float lg[16][NEXP];
    __shared__ float pr[16][NEXP];
    int tid = threadIdx.x;
    int e = tid & 15, tok = tid >> 4;
    for (int i = tid; i < CDIM * NEXP; i += 256) wgs[i & 15][i >> 4] = wg[i];
    int s0 = blockIdx.x * 16;
    for (int i = tid; i < 16 * CDIM; i += 256)
        ts[i >> 8][i & 255] = g_t[(size_t)(s0 + (i >> 8)) * CDIM + (i & 255)];
    __syncthreads();

    float part[32];
#pragma unroll
    for (int j = 0; j < 32; j++) {
        float a = 0.f;
#pragma unroll
        for (int i = 0; i < 8; i++) {
            int c = j + 32 * i;
            a = __fmaf_rn(ts[tok][c], wgs[e][c], a);
        }
        part[j] = a;
    }
#pragma unroll
    for (int off = 16; off > 0; off >>= 1)
#pragma unroll
        for (int j = 0; j < 16; j++)
            if (j < off) part[j] = __fadd_rn(part[j], part[j + off]);
    lg[tok][e] = part[0];
    __syncthreads();

    if (e == 0) {
        float l[NEXP];
        float m = -INFINITY;
        for (int j = 0; j < NEXP; j++) { l[j] = lg[tok][j]; m = fmaxf(m, l[j]); }
        float ex[NEXP];
        float sum = 0.f;
        for (int j = 0; j < NEXP; j++) {
            ex[j] = expf(__fsub_rn(l[j], m));
            sum = __fadd_rn(sum, ex[j]);
        }
        float p[NEXP];
        int i1 = 0; float b1 = -1.f;
        for (int j = 0; j < NEXP; j++) {
            p[j] = __fdiv_rn(ex[j], sum);
            pr[tok][j] = p[j];
            if (p[j] > b1) { b1 = p[j]; i1 = j; }
        }
        int i2 = -1; float b2 = -2.f;
        for (int j = 0; j < NEXP; j++) {
            if (j == i1) continue;
            if (p[j] > b2) { b2 = p[j]; i2 = j; }
        }
        int s = s0 + tok;
        g_idx1[s] = i1; g_idx2[s] = i2;
        g_gate1[s] = p[i1]; g_gate2[s] = p[i2];
        g_keep2a[s] = (p[i2] > 0.2f) ? 1 : 0;
    }
    __syncthreads();
    if (tok == 0) {
        float a = 0.f;
        for (int j = 0; j < 16; j++) a += pr[j][e];
        atomicAdd(&g_probsum[e], a);
    }
}

// ---------------- phase 1: per-chunk expert counts --------------------------
__global__ void count_kernel() {
    __shared__ short c1s[128 * NEXP];
    __shared__ short c2s[128 * NEXP];
    int tid = threadIdx.x;
    int chunk = blockIdx.x * 128 + tid;
#pragma unroll
    for (int e = 0; e < NEXP; e++) { c1s[tid * NEXP + e] = 0; c2s[tid * NEXP + e] = 0; }
    int s0 = chunk * 16;
    for (int i = 0; i < 16; i++) {
        int s = s0 + i;
        c1s[tid * NEXP + g_idx1[s]]++;
        if (g_keep2a[s]) c2s[tid * NEXP + g_idx2[s]]++;
    }
#pragma unroll
    for (int e = 0; e < NEXP; e++) {
        g_ccnt1[chunk * NEXP + e] = c1s[tid * NEXP + e];
        g_ccnt2[chunk * NEXP + e] = c2s[tid * NEXP + e];
    }
}

// ---------------- phase 2: exclusive prefix over chunks + totals + loss -----
__global__ void scan_chunks_kernel(int m) {
    __shared__ int tot1s[NEXP];
    int t = threadIdx.x;
    int w = t >> 5, lane = t & 31;
    int carry1 = 0, carry2 = 0;
    for (int it = 0; it < NCHUNK / 32; it++) {
        int chunk = it * 32 + lane;
        int v1 = g_ccnt1[chunk * NEXP + w], v2 = g_ccnt2[chunk * NEXP + w];
        int s1 = v1, s2 = v2;
#pragma unroll
        for (int o = 1; o < 32; o <<= 1) {
            int n1 = __shfl_up_sync(0xffffffffu, s1, o);
            int n2 = __shfl_up_sync(0xffffffffu, s2, o);
            if (lane >= o) { s1 += n1; s2 += n2; }
        }
        g_cbase1[chunk * NEXP + w] = s1 - v1 + carry1;
        g_cbase2[chunk * NEXP + w] = s2 - v2 + carry2;
        carry1 += __shfl_sync(0xffffffffu, s1, 31);
        carry2 += __shfl_sync(0xffffffffu, s2, 31);
    }
    if (lane == 31) {
        tot1s[w] = carry1;
        g_tot1[w] = carry1;
        int used = carry1 + carry2;
        g_cnt[w] = used > CAP ? CAP : used;
    }
    __syncthreads();
    if (t == 0) {
        float l = 0.f;
        for (int e = 0; e < NEXP; e++)
            l += ((float)tot1s[e] / (float)S_TOK) * (g_probsum[e] / (float)S_TOK);
        g_loss[m] = l * (float)NEXP * 0.01f;
    }
}

// ---------------- phase 3: per-token positions/coefs ------------------------
__global__ void apply_kernel() {
    __shared__ int c1s[128 * NEXP];
    __shared__ int c2s[128 * NEXP];
    int tid = threadIdx.x;
    int chunk = blockIdx.x * 128 + tid;
#pragma unroll
    for (int e = 0; e < NEXP; e++) {
        c1s[tid * NEXP + e] = g_cbase1[chunk * NEXP + e];
        c2s[tid * NEXP + e] = g_cbase2[chunk * NEXP + e];
    }
    int s0 = chunk * 16;
    for (int i = 0; i < 16; i++) {
        int s = s0 + i;
        int e1 = g_idx1[s];
        int pos1 = c1s[tid * NEXP + e1]++;
        int e2 = g_idx2[s];
        int k2a = (int)g_keep2a[s];
        int pos2 = 0;
        if (k2a) pos2 = c2s[tid * NEXP + e2]++ + g_tot1[e2];
        int keep1 = (pos1 < CAP);
        int keep2 = k2a && (pos2 < CAP);
        float gate1 = g_gate1[s], gate2 = g_gate2[s];
        float denom = __fadd_rn(__fadd_rn(gate1, __fmul_rn(gate2, (float)k2a)), 1e-9f);
        g_c1[s] = keep1 ? __fdiv_rn(gate1, denom) : 0.f;
        g_c2[s] = keep2 ? __fdiv_rn(gate2, denom) : 0.f;
        g_d1[s] = keep1 ? (e1 * CAP + pos1) : -1;
        g_d2[s] = keep2 ? (e2 * CAP + pos2) : -1;
    }
}

// ---------------- dispatch: scatter token rows into expert buffers ----------
__global__ void scatter_kernel() {
    int gw = (blockIdx.x * blockDim.x + threadIdx.x) >> 5;
    int lane = threadIdx.x & 31;
    if (gw >= S_TOK) return;
    int s = gw;
    const float4* trow = (const float4*)(g_t + (size_t)s * CDIM);
    float4 v0 = trow[lane], v1 = trow[lane + 32];
    int d1 = g_d1[s], d2 = g_d2[s];
    if (d1 >= 0) {
        float4* o = (float4*)(g_buf + (size_t)d1 * CDIM);
        o[lane] = v0; o[lane + 32] = v1;
    }
    if (d2 >= 0) {
        float4* o = (float4*)(g_buf + (size_t)d2 * CDIM);
        o[lane] = v0; o[lane + 32] = v1;
    }
}

// ---------------- tensor-core GEMM: bf16x2 (3-product), 128x128 tile --------
// k-tile 16. smem planes: packed bf16 pairs along k, [k2=8][dim] stride 136
// words -> fragment LDS banks tig*8+g, conflict-free. Warp tile m64n32.
template<int KDIM, int NDIM, bool PHASE1>
__global__ void __launch_bounds__(256)
gemm_tc_kernel(const float* __restrict__ Bw, const float* __restrict__ bias) {
    const int e = blockIdx.z;
    if ((int)(blockIdx.y * 128) >= g_cnt[e]) return;   // skip empty row tiles
    const float* A = (PHASE1 ? g_buf : g_h) + (size_t)e * CAP * KDIM + (size_t)blockIdx.y * 128 * KDIM;
    const float* B = Bw + (size_t)e * KDIM * NDIM + blockIdx.x * 128;
    float* Cp = (PHASE1 ? g_h : g_eo) + (size_t)e * CAP * NDIM
              + (size_t)blockIdx.y * 128 * NDIM + blockIdx.x * 128;

    __shared__ uint32_t A0s[2][8][136], A1s[2][8][136];
    __shared__ uint32_t B0s[2][8][136], B1s[2][8][136];

    int tid = threadIdx.x, lane = tid & 31, wid = tid >> 5;
    int wm = wid >> 2, wn = wid & 3;        // warp tile: m = wm*64, n = wn*32
    int g = lane >> 2, tig = lane & 3;
    // A fill: row am, k-block k0 (8 consecutive k = 2 float4 = 4 pairs)
    int am = tid >> 1, ak0 = (tid & 1) * 8;
    // B fill: k-pair kk (2 k-rows), n-quad bn
    int bkk = tid >> 5, bn = (tid & 31) * 4;

    float c[4][4][4];
#pragma unroll
    for (int mi = 0; mi < 4; mi++)
#pragma unroll
        for (int ni = 0; ni < 4; ni++)
#pragma unroll
            for (int q = 0; q < 4; q++) c[mi][ni][q] = 0.f;

    // ---- fill helpers (inline) ----
    // preload k-tile 0
    {
        float4 fa0 = *(const float4*)(A + (size_t)am * KDIM + ak0);
        float4 fa1 = *(const float4*)(A + (size_t)am * KDIM + ak0 + 4);
        float xs[8] = {fa0.x, fa0.y, fa0.z, fa0.w, fa1.x, fa1.y, fa1.z, fa1.w};
#pragma unroll
        for (int j = 0; j < 4; j++) {
            uint32_t ph, pl;
            bf16x2_split(xs[2 * j], xs[2 * j + 1], ph, pl);
            A0s[0][ak0 / 2 + j][am] = ph;
            A1s[0][ak0 / 2 + j][am] = pl;
        }
        float4 fb0 = *(const float4*)(B + (size_t)(2 * bkk) * NDIM + bn);
        float4 fb1 = *(const float4*)(B + (size_t)(2 * bkk + 1) * NDIM + bn);
        float lo[4] = {fb0.x, fb0.y, fb0.z, fb0.w};
        float hi[4] = {fb1.x, fb1.y, fb1.z, fb1.w};
#pragma unroll
        for (int j = 0; j < 4; j++) {
            uint32_t ph, pl;
            bf16x2_split(lo[j], hi[j], ph, pl);
            B0s[0][bkk][bn + j] = ph;
            B1s[0][bkk][bn + j] = pl;
        }
    }
    __syncthreads();

    const int NT = KDIM / 16;
    int buf = 0;
    for (int t = 0; t < NT; t++) {
        float4 nfa0, nfa1, nfb0, nfb1;
        const bool hn = (t + 1 < NT);
        if (hn) {
            nfa0 = *(const float4*)(A + (size_t)am * KDIM + (t + 1) * 16 + ak0);
            nfa1 = *(const float4*)(A + (size_t)am * KDIM + (t + 1) * 16 + ak0 + 4);
            nfb0 = *(const float4*)(B + (size_t)((t + 1) * 16 + 2 * bkk) * NDIM + bn);
            nfb1 = *(const float4*)(B + (size_t)((t + 1) * 16 + 2 * bkk + 1) * NDIM + bn);
        }
        // fragments
        uint32_t a0f[4][4], a1f[4][4], b0f[4][2], b1f[4][2];
#pragma unroll
        for (int mi = 0; mi < 4; mi++) {
            int mb = wm * 64 + mi * 16;
            a0f[mi][0] = A0s[buf][tig][mb + g];
            a0f[mi][1] = A0s[buf][tig][mb + g + 8];
            a0f[mi][2] = A0s[buf][tig + 4][mb + g];
            a0f[mi][3] = A0s[buf][tig + 4][mb + g + 8];
            a1f[mi][0] = A1s[buf][tig][mb + g];
            a1f[mi][1] = A1s[buf][tig][mb + g + 8];
            a1f[mi][2] = A1s[buf][tig + 4][mb + g];
            a1f[mi][3] = A1s[buf][tig + 4][mb + g + 8];
        }
#pragma unroll
        for (int ni = 0; ni < 4; ni++) {
            int nb0 = wn * 32 + ni * 8;
            b0f[ni][0] = B0s[buf][tig][nb0 + g];
            b0f[ni][1] = B0s[buf][tig + 4][nb0 + g];
            b1f[ni][0] = B1s[buf][tig][nb0 + g];
            b1f[ni][1] = B1s[buf][tig + 4][nb0 + g];
        }
        // 3-product bf16x2
#pragma unroll
        for (int mi = 0; mi < 4; mi++)
#pragma unroll
            for (int ni = 0; ni < 4; ni++) {
                mma_bf16(c[mi][ni], a0f[mi][0], a0f[mi][1], a0f[mi][2], a0f[mi][3],
                         b1f[ni][0], b1f[ni][1]);
                mma_bf16(c[mi][ni], a1f[mi][0], a1f[mi][1], a1f[mi][2], a1f[mi][3],
                         b0f[ni][0], b0f[ni][1]);
                mma_bf16(c[mi][ni], a0f[mi][0], a0f[mi][1], a0f[mi][2], a0f[mi][3],
                         b0f[ni][0], b0f[ni][1]);
            }
        if (hn) {
            int nb = buf ^ 1;
            float xs[8] = {nfa0.x, nfa0.y, nfa0.z, nfa0.w, nfa1.x, nfa1.y, nfa1.z, nfa1.w};
#pragma unroll
            for (int j = 0; j < 4; j++) {
                uint32_t ph, pl;
                bf16x2_split(xs[2 * j], xs[2 * j + 1], ph, pl);
                A0s[nb][ak0 / 2 + j][am] = ph;
                A1s[nb][ak0 / 2 + j][am] = pl;
            }
            float lo[4] = {nfb0.x, nfb0.y, nfb0.z, nfb0.w};
            float hi[4] = {nfb1.x, nfb1.y, nfb1.z, nfb1.w};
#pragma unroll
            for (int j = 0; j < 4; j++) {
                uint32_t ph, pl;
                bf16x2_split(lo[j], hi[j], ph, pl);
                B0s[nb][bkk][bn + j] = ph;
                B1s[nb][bkk][bn + j] = pl;
            }
        }
        __syncthreads();
        buf ^= 1;
    }

    // epilogue: bias (+ leaky for phase1)
    const float* bv = bias + e * NDIM + blockIdx.x * 128;
    int r = lane >> 2, cg = (lane & 3) * 2;
#pragma unroll
    for (int mi = 0; mi < 4; mi++) {
#pragma unroll
        for (int ni = 0; ni < 4; ni++) {
            int ml = wm * 64 + mi * 16 + r;
            int nl = wn * 32 + ni * 8 + cg;
            float bb0 = bv[nl], bb1 = bv[nl + 1];
            float v0 = c[mi][ni][0] + bb0;
            float v1 = c[mi][ni][1] + bb1;
            float v2 = c[mi][ni][2] + bb0;
            float v3 = c[mi][ni][3] + bb1;
            if (PHASE1) {
                v0 = v0 > 0.f ? v0 : 0.01f * v0;
                v1 = v1 > 0.f ? v1 : 0.01f * v1;
                v2 = v2 > 0.f ? v2 : 0.01f * v2;
                v3 = v3 > 0.f ? v3 : 0.01f * v3;
            }
            float2 p0 = {v0, v1}, p1 = {v2, v3};
            *(float2*)(Cp + (size_t)ml * NDIM + nl) = p0;
            *(float2*)(Cp + (size_t)(ml + 8) * NDIM + nl) = p1;
        }
    }
}

// ---------------- combine: gather expert outputs back to tokens -------------
__global__ void combine_kernel(int m) {
    int gw = (blockIdx.x * blockDim.x + threadIdx.x) >> 5;
    int lane = threadIdx.x & 31;
    if (gw >= S_TOK) return;
    int s = gw;
    float c1 = g_c1[s], c2 = g_c2[s];
    int d1 = g_d1[s], d2 = g_d2[s];
    float4 o0 = {0.f, 0.f, 0.f, 0.f}, o1 = {0.f, 0.f, 0.f, 0.f};
    if (d1 >= 0) {
        const float4* rr = (const float4*)(g_eo + (size_t)d1 * CDIM);
        float4 a = rr[lane], b = rr[lane + 32];
        o0.x += c1 * a.x; o0.y += c1 * a.y; o0.z += c1 * a.z; o0.w += c1 * a.w;
        o1.x += c1 * b.x; o1.y += c1 * b.y; o1.z += c1 * b.z; o1.w += c1 * b.w;
    }
    if (d2 >= 0) {
        const float4* rr = (const float4*)(g_eo + (size_t)d2 * CDIM);
        float4 a = rr[lane], b = rr[lane + 32];
        o0.x += c2 * a.x; o0.y += c2 * a.y; o0.z += c2 * a.z; o0.w += c2 * a.w;
        o1.x += c2 * b.x; o1.y += c2 * b.y; o1.z += c2 * b.z; o1.w += c2 * b.w;
    }
    float4* y = (float4*)((m == 0 ? g_y0 : g_y1) + (size_t)s * CDIM);
    y[lane] = o0; y[lane + 32] = o1;
}

// ---------------- fusion gate -----------------------------------------------
__global__ void gatecoef_kernel(const float* __restrict__ gcw, const float* __restrict__ gcb,
                                const float* __restrict__ gsw, const float* __restrict__ gsb) {
    int gw = (blockIdx.x * blockDim.x + threadIdx.x) >> 5;
    int lane = threadIdx.x & 31;
    if (gw >= S_TOK) return;
    int s = gw;
    const float* ch = g_y0 + (size_t)s * CDIM;
    const float* sp = g_y1 + (size_t)s * CDIM;
    float vc = 0.f, vs = 0.f;
    for (int k = lane; k < CDIM; k += 32) {
        float a = ch[k], b = sp[k];
        vc += a * gcw[k] + b * gcw[CDIM + k];
        vs += a * gsw[k] + b * gsw[CDIM + k];
    }
#pragma unroll
    for (int o = 16; o > 0; o >>= 1) {
        vc += __shfl_xor_sync(0xffffffffu, vc, o);
        vs += __shfl_xor_sync(0xffffffffu, vs, o);
    }
    if (lane == 0) {
        float d = (vs + gsb[0]) - (vc + gcb[0]);
        g_a0[s] = 1.f / (1.f + expf(d));
    }
}

// ---------------- final output ----------------------------------------------
__global__ void output_kernel(float* __restrict__ out) {
    __shared__ float sm[32][33];
    int b = blockIdx.x, c0 = blockIdx.y * 32, hw0 = blockIdx.z * 32;
    int tx = threadIdx.x, ty = threadIdx.y;
    int s = b * 4096 + hw0 + ty;
    float a0 = g_a0[s];
    float chv = g_y0[(size_t)s * CDIM + c0 + tx];
    float spv = g_y1[(size_t)s * CDIM + c0 + tx];
    sm[tx][ty] = a0 * chv + (1.f - a0) * spv;
    __syncthreads();
    out[((size_t)(b * CDIM + c0 + ty)) * 4096 + hw0 + tx] = sm[ty][tx];
}

__global__ void write_loss_kernel(float* __restrict__ out, int n) {
    float l = (g_loss[0] + g_loss[1]) * 0.5f;
    for (int i = threadIdx.x; i < n; i += blockDim.x) out[i] = l;
}

// ---------------- launch ----------------------------------------------------
extern "C" void kernel_launch(void* const* d_in, const int* in_sizes, int n_in,
                              void* d_out, int out_size) {
    const float* x      = (const float*)d_in[0];
    const float* audio  = (const float*)d_in[1];
    const float* wg_c   = (const float*)d_in[2];
    const float* w1_c   = (const float*)d_in[3];
    const float* b1_c   = (const float*)d_in[4];
    const float* w2_c   = (const float*)d_in[5];
    const float* b2_c   = (const float*)d_in[6];
    const float* wg_s   = (const float*)d_in[7];
    const float* w1_s   = (const float*)d_in[8];
    const float* b1_s   = (const float*)d_in[9];
    const float* w2_s   = (const float*)d_in[10];
    const float* b2_s   = (const float*)d_in[11];
    const float* gate_c_w = (const float*)d_in[12];
    const float* gate_c_b = (const float*)d_in[13];
    const float* gate_s_w = (const float*)d_in[14];
    const float* gate_s_b = (const float*)d_in[15];
    float* out = (float*)d_out;

    build_t_kernel<<<dim3(8, 8, 128), dim3(32, 32)>>>(x, audio);

    const int warp_blocks = (S_TOK * 32) / 256;  // 4096

    for (int m = 0; m < 2; m++) {
        const float* wg = m == 0 ? wg_c : wg_s;
        const float* w1 = m == 0 ? w1_c : w1_s;
        const float* b1 = m == 0 ? b1_c : b1_s;
        const float* w2 = m == 0 ? w2_c : w2_s;
        const float* b2 = m == 0 ? b2_c : b2_s;
        zero16_kernel<<<1, 32>>>();
        route_kernel<<<S_TOK / 16, 256>>>(wg);
        count_kernel<<<NCHUNK / 128, 128>>>();
        scan_chunks_kernel<<<1, 512>>>(m);
        apply_kernel<<<NCHUNK / 128, 128>>>();
        scatter_kernel<<<warp_blocks, 256>>>();
        gemm_tc_kernel<CDIM, HID, true><<<dim3(HID / 128, CAP / 128, NEXP), 256>>>(w1, b1);
        gemm_tc_kernel<HID, CDIM, false><<<dim3(CDIM / 128, CAP / 128, NEXP), 256>>>(w2, b2);
        combine_kernel<<<warp_blocks, 256>>>(m);
    }

    gatecoef_kernel<<<warp_blocks, 256>>>(gate_c_w, gate_c_b, gate_s_w, gate_s_b);
    output_kernel<<<dim3(8, 8, 128), dim3(32, 32)>>>(out);
    if (out_size > NPIX) {
        write_loss_kernel<<<1, 256>>>(out + NPIX, out_size - NPIX);
    }
}